// round 11
// baseline (speedup 1.0000x reference)
#include <cuda_runtime.h>
#include <cuda_bf16.h>
#include <cstdint>

#define NS   16
#define NP   2048
#define DIM  64
#define KNN  16
#define QT   128            // queries per CTA
#define NB   128            // points per tile
#define NTILE (NP / NB)     // 16
#define TPB  256            // 8 warps

// ---- bf16 3-split of h + fp32 norms (device scratch; no allocs) ----
__device__ uint4 g_h0[(size_t)NS * NP * DIM / 8];   // 4 MB each (bf16 rows of 64)
__device__ uint4 g_h1[(size_t)NS * NP * DIM / 8];
__device__ uint4 g_h2[(size_t)NS * NP * DIM / 8];
__device__ float g_norm[(size_t)NS * NP];

// B tile smem: 3 splits x 128 rows x 72 bf16 (144B padded stride -> conflict-free frags)
#define BSTRIDE   144
#define BSPLIT_SZ (NB * BSTRIDE)        // 18432
#define SM_PN     (3 * BSPLIT_SZ)       // 55296: 128 floats
#define SM_TOT    (SM_PN + 512)
// merge scratch overlays B region after last tile: 128 keys x 32 entries
// scr_d at smem+0 (16KB), scr_i at smem+16384 (16KB)

// mma.sync m16n8k16 row.col f32.bf16.bf16.f32 — baseline PTX, works on sm_103
__device__ __forceinline__ void mma16816(float d[4],
                                         uint32_t a0, uint32_t a1, uint32_t a2, uint32_t a3,
                                         uint32_t b0, uint32_t b1) {
    asm volatile("mma.sync.aligned.m16n8k16.row.col.f32.bf16.bf16.f32 "
        "{%0,%1,%2,%3}, {%4,%5,%6,%7}, {%8,%9}, {%0,%1,%2,%3};"
        : "+f"(d[0]), "+f"(d[1]), "+f"(d[2]), "+f"(d[3])
        : "r"(a0), "r"(a1), "r"(a2), "r"(a3), "r"(b0), "r"(b1));
}

// =================== kernel 0: fp32 -> 3x bf16 splits ======================
__global__ void split_kernel(const float* __restrict__ h)
{
    int i = blockIdx.x * blockDim.x + threadIdx.x;     // handles 4 elems
    if (i >= NS * NP * DIM / 4) return;
    float4 v = reinterpret_cast<const float4*>(h)[i];
    ushort4 s0, s1, s2;
    float f, r;
    #define SPLIT1(comp, fld)                                             \
        f = v.comp;                                                       \
        s0.fld = __bfloat16_as_ushort(__float2bfloat16_rn(f));            \
        r = f - __bfloat162float(__ushort_as_bfloat16(s0.fld));           \
        s1.fld = __bfloat16_as_ushort(__float2bfloat16_rn(r));            \
        r = r - __bfloat162float(__ushort_as_bfloat16(s1.fld));           \
        s2.fld = __bfloat16_as_ushort(__float2bfloat16_rn(r));
    SPLIT1(x, x) SPLIT1(y, y) SPLIT1(z, z) SPLIT1(w, w)
    #undef SPLIT1
    reinterpret_cast<ushort4*>(g_h0)[i] = s0;
    reinterpret_cast<ushort4*>(g_h1)[i] = s1;
    reinterpret_cast<ushort4*>(g_h2)[i] = s2;
}

// =================== kernel 1: exact fp32 norms ============================
__global__ void norm_kernel(const float* __restrict__ h)
{
    int p = blockIdx.x * blockDim.x + threadIdx.x;
    if (p >= NS * NP) return;
    const float4* row = reinterpret_cast<const float4*>(h + (size_t)p * DIM);
    float n = 0.0f;
    #pragma unroll
    for (int i = 0; i < DIM / 4; i++) {
        float4 v = row[i];
        n += v.x * v.x + v.y * v.y + v.z * v.z + v.w * v.w;
    }
    g_norm[p] = n;
}

// =================== kernel 2: HMMA GEMM + fused top-K =====================
__global__ __launch_bounds__(TPB, 1)
void knn_main_kernel(float* __restrict__ out_dist,
                     float* __restrict__ out_dst,
                     float* __restrict__ out_src)
{
    extern __shared__ char smem[];
    float* pnorm = reinterpret_cast<float*>(smem + SM_PN);
    float* scr_d = reinterpret_cast<float*>(smem);            // merge scratch (reuses B)
    int*   scr_i = reinterpret_cast<int*>(smem + 16384);

    const int tid  = threadIdx.x;
    const int warp = tid >> 5;
    const int lane = tid & 31;
    const int g    = lane >> 2;      // group 0..7
    const int tig  = lane & 3;       // thread-in-group
    const int s    = blockIdx.x >> 4;
    const int qt   = blockIdx.x & 15;
    const int arow0 = s * NP + qt * QT;      // global row of first query in CTA

    const int r0 = warp * 16 + g;            // query row (list 0); list 1 = r0 + 8
    const float qn0 = g_norm[arow0 + r0];
    const float qn1 = g_norm[arow0 + r0 + 8];

    // ---- A fragments from global, resident all kernel: [split][kstep][4] ----
    uint32_t afr[3][4][4];
    {
        const uint32_t* ga[3] = { reinterpret_cast<const uint32_t*>(g_h0),
                                  reinterpret_cast<const uint32_t*>(g_h1),
                                  reinterpret_cast<const uint32_t*>(g_h2) };
        const size_t rA = (size_t)(arow0 + r0) * 32;       // 64 bf16 = 32 words/row
        const size_t rB = (size_t)(arow0 + r0 + 8) * 32;
        #pragma unroll
        for (int sp = 0; sp < 3; sp++)
            #pragma unroll
            for (int ks = 0; ks < 4; ks++) {
                int w0 = tig + 8 * ks;                     // word = cols 2tig+16ks..+1
                afr[sp][ks][0] = ga[sp][rA + w0];
                afr[sp][ks][1] = ga[sp][rB + w0];
                afr[sp][ks][2] = ga[sp][rA + w0 + 4];      // cols +8
                afr[sp][ks][3] = ga[sp][rB + w0 + 4];
            }
    }

    // ---- per-row top-K lists (thread owns rows r0 and r0+8) ----
    float bd0[KNN], bd1[KNN];
    int   bi0[KNN], bi1[KNN];
    #pragma unroll
    for (int k = 0; k < KNN; k++) {
        bd0[k] = 3.4e38f; bd1[k] = 3.4e38f; bi0[k] = 0; bi1[k] = 0;
    }

    const int ta[6] = {0, 0, 1, 1, 0, 2};
    const int tb[6] = {0, 1, 0, 1, 2, 0};

    for (int tile = 0; tile < NTILE; tile++) {
        __syncthreads();   // prior tile's B-fragment LDS complete
        {   // ---- stage B tile: 3 splits, padded conflict-free layout ----
            const int brow0 = s * NP + tile * NB;
            for (int i = tid; i < NB * 8; i += TPB) {      // 8 uint4 per row
                int r = i >> 3, c = i & 7;
                char* dst = smem + (size_t)r * BSTRIDE + c * 16;
                size_t gi = (size_t)(brow0 + r) * 8 + c;
                *reinterpret_cast<uint4*>(dst)                  = g_h0[gi];
                *reinterpret_cast<uint4*>(dst + BSPLIT_SZ)      = g_h1[gi];
                *reinterpret_cast<uint4*>(dst + 2 * BSPLIT_SZ)  = g_h2[gi];
            }
            if (tid < NB) pnorm[tid] = g_norm[brow0 + tid];
        }
        __syncthreads();

        for (int np = 0; np < 8; np++) {                   // 2 n-chunks (16 points) per pass
            // ---- B fragments: [split][kstep][nchunk01][2] ----
            uint32_t bf[3][4][2][2];
            #pragma unroll
            for (int sp = 0; sp < 3; sp++)
                #pragma unroll
                for (int ks = 0; ks < 4; ks++)
                    #pragma unroll
                    for (int n01 = 0; n01 < 2; n01++) {
                        int prow = (np * 2 + n01) * 8 + g;
                        const char* base = smem + sp * BSPLIT_SZ
                                         + (size_t)prow * BSTRIDE + (tig + 8 * ks) * 4;
                        bf[sp][ks][n01][0] = *reinterpret_cast<const uint32_t*>(base);
                        bf[sp][ks][n01][1] = *reinterpret_cast<const uint32_t*>(base + 16);
                    }

            float d[2][4] = { {0.f,0.f,0.f,0.f}, {0.f,0.f,0.f,0.f} };
            #pragma unroll
            for (int ks = 0; ks < 4; ks++)
                #pragma unroll
                for (int t = 0; t < 6; t++)
                    #pragma unroll
                    for (int n01 = 0; n01 < 2; n01++)
                        mma16816(d[n01],
                                 afr[ta[t]][ks][0], afr[ta[t]][ks][1],
                                 afr[ta[t]][ks][2], afr[ta[t]][ks][3],
                                 bf[tb[t]][ks][n01][0], bf[tb[t]][ks][n01][1]);

            // ---- fused epilogue: dist + top-K insert (ascending index order) ----
            #pragma unroll
            for (int n01 = 0; n01 < 2; n01++) {
                int col0 = (np * 2 + n01) * 8 + 2 * tig;
                float pn0 = pnorm[col0], pn1 = pnorm[col0 + 1];
                int jb = tile * NB + col0;
                #define INS(LD, LI, DIST, IDX)                                  \
                    if ((DIST) < LD[KNN - 1]) {                                  \
                        float _dd = (DIST); int _di = (IDX);                     \
                        _Pragma("unroll")                                        \
                        for (int k = 0; k < KNN; k++)                            \
                            if (_dd < LD[k]) {                                   \
                                float _td = LD[k]; int _ti = LI[k];              \
                                LD[k] = _dd; LI[k] = _di; _dd = _td; _di = _ti;  \
                            }                                                    \
                    }
                INS(bd0, bi0, fmaf(-2.0f, d[n01][0], qn0 + pn0), jb)
                INS(bd0, bi0, fmaf(-2.0f, d[n01][1], qn0 + pn1), jb + 1)
                INS(bd1, bi1, fmaf(-2.0f, d[n01][2], qn1 + pn0), jb)
                INS(bd1, bi1, fmaf(-2.0f, d[n01][3], qn1 + pn1), jb + 1)
            }
        }
    }

    // =============== cross-thread merge: 4 threads per row ===================
    __syncthreads();   // B region now reusable as scratch

    // merge src (smem list, sorted lex) into (LD, LI) with index tie-break
    #define MERGE(LD, LI, OFF)                                                  \
        for (int j = 0; j < KNN; j++) {                                         \
            float dj = scr_d[(OFF) + j]; int ij = scr_i[(OFF) + j];             \
            if (dj < LD[KNN - 1] || (dj == LD[KNN - 1] && ij < LI[KNN - 1])) {  \
                float _dd = dj; int _di = ij;                                   \
                _Pragma("unroll")                                               \
                for (int k = 0; k < KNN; k++) {                                 \
                    bool sw = (_dd < LD[k]) || (_dd == LD[k] && _di < LI[k]);   \
                    if (sw) {                                                   \
                        float _td = LD[k]; int _ti = LI[k];                     \
                        LD[k] = _dd; LI[k] = _di; _dd = _td; _di = _ti;         \
                    }                                                           \
                }                                                               \
            }                                                                   \
        }

    const int key  = (warp * 8 + g) * 2;        // two slots per (warp,g)
    // round 1: tig 1 -> slot 0, tig 3 -> slot 1
    if (tig & 1) {
        int base = (key + (tig >> 1)) * 32;
        #pragma unroll
        for (int k = 0; k < KNN; k++) {
            scr_d[base + k]      = bd0[k]; scr_i[base + k]      = bi0[k];
            scr_d[base + 16 + k] = bd1[k]; scr_i[base + 16 + k] = bi1[k];
        }
    }
    __syncwarp();
    if (!(tig & 1)) {
        int base = (key + (tig >> 1)) * 32;
        MERGE(bd0, bi0, base)
        MERGE(bd1, bi1, base + 16)
    }
    __syncwarp();
    // round 2: tig 2 -> slot 0; tig 0 merges
    if (tig == 2) {
        int base = key * 32;
        #pragma unroll
        for (int k = 0; k < KNN; k++) {
            scr_d[base + k]      = bd0[k]; scr_i[base + k]      = bi0[k];
            scr_d[base + 16 + k] = bd1[k]; scr_i[base + 16 + k] = bi1[k];
        }
    }
    __syncwarp();
    if (tig == 0) {
        int base = key * 32;
        MERGE(bd0, bi0, base)
        MERGE(bd1, bi1, base + 16)

        const float offs = (float)(s * NP);
        const int   q0   = arow0 + r0;         // global row ids
        const int   q1   = q0 + 8;
        size_t ob0 = (size_t)q0 * KNN, ob1 = (size_t)q1 * KNN;
        #pragma unroll
        for (int k = 0; k < KNN; k++) {
            out_dist[ob0 + k] = bd0[k];
            out_dst [ob0 + k] = (float)bi0[k] + offs;
            out_src [ob0 + k] = (float)q0;
            out_dist[ob1 + k] = bd1[k];
            out_dst [ob1 + k] = (float)bi1[k] + offs;
            out_src [ob1 + k] = (float)q1;
        }
    }
}

extern "C" void kernel_launch(void* const* d_in, const int* in_sizes, int n_in,
                              void* d_out, int out_size)
{
    const float* h = (const float*)d_in[0];

    float* out      = (float*)d_out;
    const size_t nE = (size_t)NS * NP * KNN;
    float* out_dist = out;
    float* out_dst  = out + nE;
    float* out_src  = out + 2 * nE;

    split_kernel<<<(NS * NP * DIM / 4 + 255) / 256, 256>>>(h);
    norm_kernel<<<(NS * NP + 127) / 128, 128>>>(h);

    cudaFuncSetAttribute(knn_main_kernel,
                         cudaFuncAttributeMaxDynamicSharedMemorySize, SM_TOT);
    knn_main_kernel<<<NS * (NP / QT), TPB, SM_TOT>>>(out_dist, out_dst, out_src);
}